// round 7
// baseline (speedup 1.0000x reference)
#include <cuda_runtime.h>
#include <cstdint>

#define FILLV (-1000.0f)
#define NEG_BIG (-3.0e38f)

// Per-batch scratch (allocation-free rule: __device__ globals).
__device__ float g_total[512];
__device__ float g_real[512];

// ---- f32x2 / b64 helpers -------------------------------------------------
__device__ __forceinline__ unsigned long long pk2(float x, float y) {
    unsigned long long r;
    asm("mov.b64 %0, {%1, %2};" : "=l"(r) : "f"(x), "f"(y));
    return r;
}
__device__ __forceinline__ void upk2(unsigned long long a, float& x, float& y) {
    asm("mov.b64 {%0, %1}, %2;" : "=f"(x), "=f"(y) : "l"(a));
}
__device__ __forceinline__ unsigned long long fma2(unsigned long long a,
                                                   unsigned long long b,
                                                   unsigned long long c) {
    unsigned long long r;
    asm("fma.rn.f32x2 %0, %1, %2, %3;" : "=l"(r) : "l"(a), "l"(b), "l"(c));
    return r;
}
__device__ __forceinline__ unsigned long long add2(unsigned long long a,
                                                   unsigned long long b) {
    unsigned long long r;
    asm("add.rn.f32x2 %0, %1, %2;" : "=l"(r) : "l"(a), "l"(b));
    return r;
}

// ---- forward (total path score) kernel -----------------------------------
// 4 batches per CTA. grid = 128, block = 512 (16 warps -> 4 warps/SMSP).
// Thread t: column jj = t & 127, quarter q = t >> 7 (rows q*32 .. q*32+31).
// Phase 0: every thread processes its 32-row slice for ALL 4 batches (ILP-4).
// Phases 1/2: quarter q OWNS batch q (4 batches fully parallel).
// Register tables (shared across batches): Tc2[16] + Ep[16] = 64 regs.
__global__ void __launch_bounds__(512, 1)
crf_forward_kernel(const float* __restrict__ em, const float* __restrict__ trans) {
    __shared__ ulonglong2 shpv[4][64];   // per batch: {pre[2m],pre[2m+1] | v[2m],v[2m+1]}
    __shared__ float spc[4][512];        // per batch: per-thread partial column max
    __shared__ float spw[4][512];        // per batch: per-thread partial matvec sum
    __shared__ float scol[128];          // colmax of transitions (batch-independent)
    __shared__ float swS[4][4], swM[4][4];

    const int t  = threadIdx.x;
    const int jj = t & 127;
    const int q  = t >> 7;               // quarter index; owns batch q
    const int b0 = blockIdx.x * 4;
    const int rowbase = q * 32;

    // --- load T column slice (32 rows), colmax, packed Tc2 / Ep tables ---
    float Tcs[32];
    float tcm = NEG_BIG;
#pragma unroll
    for (int k = 0; k < 32; ++k) {
        float tv = trans[(rowbase + k) * 128 + jj];
        Tcs[k] = tv;
        tcm = fmaxf(tcm, tv);
    }
    spc[0][t] = tcm;
    __syncthreads();
    if (t < 128) {
        scol[t] = fmaxf(fmaxf(spc[0][t], spc[0][t + 128]),
                        fmaxf(spc[0][t + 256], spc[0][t + 384]));
    }
    __syncthreads();
    const float colmax = scol[jj];

    unsigned long long Tc2[16], Ep[16];
#pragma unroll
    for (int k = 0; k < 16; ++k) {
        Tc2[k] = pk2(Tcs[2 * k], Tcs[2 * k + 1]);
        Ep[k]  = pk2(expf(Tcs[2 * k] - colmax), expf(Tcs[2 * k + 1] - colmax));
    }

    // --- init state: quarter q initializes batch q ---
    {
        float p  = (jj == 126) ? 0.0f : FILLV;
        float vv = (jj == 126) ? 1.0f : 0.0f;
        int m = jj >> 1, lane = jj & 1;
        float* pvf = (float*)shpv[q];
        pvf[m * 4 + lane]     = p;
        pvf[m * 4 + 2 + lane] = vv;
    }
    float pmax = 0.0f;
    float Lacc = 0.0f;
    float vkeep = 0.0f;
    __syncthreads();

    const float* embp = em + (size_t)(b0 + q) * 512 * 126;

    // obs for step s=1 (emissions row 0), owned batch only
    float obs_c = (jj < 126) ? embp[jj] : FILLV;

    const ulonglong2* const pvA = shpv[0] + q * 16;
    const ulonglong2* const pvB = shpv[1] + q * 16;
    const ulonglong2* const pvC = shpv[2] + q * 16;
    const ulonglong2* const pvD = shpv[3] + q * 16;

    for (int s = 1; s <= 513; ++s) {
        // Prefetch next step's observation (hidden behind phase 0).
        float obs_n;
        if (s + 1 <= 512) {
            obs_n = (jj < 126) ? embp[(size_t)s * 126 + jj] : FILLV;
        } else {
            obs_n = (jj == 127) ? 0.0f : FILLV;   // END pseudo-row
        }

        // --- phase 0: max-plus + matvec over this thread's 32 rows, 4 batches ---
        float cm0A = NEG_BIG, cm1A = NEG_BIG;
        float cm0B = NEG_BIG, cm1B = NEG_BIG;
        float cm0C = NEG_BIG, cm1C = NEG_BIG;
        float cm0D = NEG_BIG, cm1D = NEG_BIG;
        unsigned long long wA = 0ULL, wB = 0ULL, wC = 0ULL, wD = 0ULL;
#pragma unroll
        for (int k = 0; k < 16; ++k) {
            ulonglong2 qA = pvA[k];
            ulonglong2 qB = pvB[k];
            ulonglong2 qC = pvC[k];
            ulonglong2 qD = pvD[k];
            float s0, s1;
            unsigned long long u;
            u = add2(qA.x, Tc2[k]); upk2(u, s0, s1);
            cm0A = fmaxf(cm0A, s0); cm1A = fmaxf(cm1A, s1);
            wA = fma2(qA.y, Ep[k], wA);
            u = add2(qB.x, Tc2[k]); upk2(u, s0, s1);
            cm0B = fmaxf(cm0B, s0); cm1B = fmaxf(cm1B, s1);
            wB = fma2(qB.y, Ep[k], wB);
            u = add2(qC.x, Tc2[k]); upk2(u, s0, s1);
            cm0C = fmaxf(cm0C, s0); cm1C = fmaxf(cm1C, s1);
            wC = fma2(qC.y, Ep[k], wC);
            u = add2(qD.x, Tc2[k]); upk2(u, s0, s1);
            cm0D = fmaxf(cm0D, s0); cm1D = fmaxf(cm1D, s1);
            wD = fma2(qD.y, Ep[k], wD);
        }
        {
            float w0, w1;
            upk2(wA, w0, w1); spc[0][t] = fmaxf(cm0A, cm1A); spw[0][t] = w0 + w1;
            upk2(wB, w0, w1); spc[1][t] = fmaxf(cm0B, cm1B); spw[1][t] = w0 + w1;
            upk2(wC, w0, w1); spc[2][t] = fmaxf(cm0C, cm1C); spw[2][t] = w0 + w1;
            upk2(wD, w0, w1); spc[3][t] = fmaxf(cm0D, cm1D); spw[3][t] = w0 + w1;
        }
        __syncthreads();

        // --- phase 1: quarter q combines + reduces its owned batch q ---
        float pnew;
        {
            float c = fmaxf(fmaxf(spc[q][jj], spc[q][jj + 128]),
                            fmaxf(spc[q][jj + 256], spc[q][jj + 384]));
            float w = (spw[q][jj] + spw[q][jj + 128]) +
                      (spw[q][jj + 256] + spw[q][jj + 384]);
            float contrib = expf(pmax + colmax - c) * w;
            pnew = obs_c + c;

            float sred = contrib, mred = pnew;
#pragma unroll
            for (int o = 16; o; o >>= 1) {
                sred += __shfl_xor_sync(0xffffffffu, sred, o);
                mred = fmaxf(mred, __shfl_xor_sync(0xffffffffu, mred, o));
            }
            if ((t & 31) == 0) {
                const int wi = (t >> 5) & 3;
                swS[q][wi] = sred; swM[q][wi] = mred;
            }
        }
        // quarter-scoped barrier (ids 1..4): quarter q only reads swS/swM[q]
        asm volatile("bar.sync %0, 128;" :: "r"(q + 1) : "memory");

        // --- phase 2: scalar combine + publish new state for owned batch ---
        {
            float S  = (swS[q][0] + swS[q][1]) + (swS[q][2] + swS[q][3]);
            float pm = fmaxf(fmaxf(swM[q][0], swM[q][1]), fmaxf(swM[q][2], swM[q][3]));
            Lacc += logf(S);
            float vv = expf(pnew - pm);
            vkeep = vv;
            int m = jj >> 1, lane = jj & 1;
            float* pvf = (float*)shpv[q];
            pvf[m * 4 + lane]     = pnew;
            pvf[m * 4 + 2 + lane] = vv;
            pmax = pm;
        }
        __syncthreads();
        obs_c = obs_n;
    }

    // --- final log-sum-exp for owned batch ---
    {
        float sred = vkeep;
#pragma unroll
        for (int o = 16; o; o >>= 1) sred += __shfl_xor_sync(0xffffffffu, sred, o);
        if ((t & 31) == 0) swS[q][(t >> 5) & 3] = sred;
    }
    asm volatile("bar.sync %0, 128;" :: "r"(q + 1) : "memory");
    if (jj == 0) {
        float Sf = (swS[q][0] + swS[q][1]) + (swS[q][2] + swS[q][3]);
        g_total[b0 + q] = pmax + logf(Sf) + Lacc;
    }
}

// ---- gold-path score kernel ----------------------------------------------
__global__ void crf_real_kernel(const float* __restrict__ em,
                                const int* __restrict__ labels,
                                const float* __restrict__ trans) {
    const int b = blockIdx.x;
    const int t = threadIdx.x;   // 128 threads
    __shared__ float sw[4];
    const int* lb = labels + b * 512;
    const float* emb = em + (size_t)b * 512 * 126;

    float acc = 0.0f;
    for (int tt = t; tt < 512; tt += 128) {
        int l0 = lb[tt];
        acc += emb[tt * 126 + l0];
        int l1 = (tt < 511) ? lb[tt + 1] : 127;     // END = L+1 = 127
        acc += trans[l0 * 128 + l1];
    }
    if (t == 0) acc += trans[126 * 128 + lb[0]];     // START = L = 126

#pragma unroll
    for (int o = 16; o; o >>= 1) acc += __shfl_xor_sync(0xffffffffu, acc, o);
    if ((t & 31) == 0) sw[t >> 5] = acc;
    __syncthreads();
    if (t == 0) g_real[b] = (sw[0] + sw[1]) + (sw[2] + sw[3]);
}

// ---- fixed-order final reduction (deterministic) -------------------------
__global__ void crf_reduce_kernel(float* __restrict__ out) {
    const int t = threadIdx.x;   // 512 threads
    __shared__ float sw[16];
    float d = g_total[t] - g_real[t];
#pragma unroll
    for (int o = 16; o; o >>= 1) d += __shfl_xor_sync(0xffffffffu, d, o);
    if ((t & 31) == 0) sw[t >> 5] = d;
    __syncthreads();
    if (t == 0) {
        float s = 0.0f;
#pragma unroll
        for (int w = 0; w < 16; ++w) s += sw[w];
        out[0] = s;
    }
}

extern "C" void kernel_launch(void* const* d_in, const int* in_sizes, int n_in,
                              void* d_out, int out_size) {
    const float* em     = (const float*)d_in[0];   // [512, 512, 126] f32
    const int*   labels = (const int*)d_in[1];     // [512, 512] i32
    const float* trans  = (const float*)d_in[2];   // [128, 128] f32

    crf_forward_kernel<<<128, 512>>>(em, trans);
    crf_real_kernel<<<512, 128>>>(em, labels, trans);
    crf_reduce_kernel<<<1, 512>>>((float*)d_out);
}